// round 9
// baseline (speedup 1.0000x reference)
#include <cuda_runtime.h>
#include <cuda_fp16.h>

#define IH 256
#define IW 256
#define NPIX (IH * IW)
#define NMAPS 88
#define SRC_ELEMS (NPIX * 3)

#define QSTRIDE 132
#define QROWS 129
#define COPYSZ (QROWS * QSTRIDE)    // 17028

#define NGROUPS (NMAPS * NPIX / 4)  // 1,441,792 (4 px per thread-group item)
#define DBLOCKS 1184                // 148 SMs x 8 resident CTAs, grid-stride
#define DTHREADS 256

// 2x2 fp16 quad, 32B: [0..3]=NW(r,g,b,0) [4..7]=NE [8..11]=SW [12..15]=SE.
// Copy (py,px): quad (ky,kx) covers rows (2ky-py, 2ky-py+1), cols (2kx-px, 2kx-px+1).
// OOB pixels stored zero -> bakes the reference's corner masks.
struct __align__(32) Quad { uint4 a, b; };
__device__ Quad g_quads[4 * COPYSZ];   // ~2.18 MB, L2-resident

__device__ __forceinline__ void px_fetch(const float* __restrict__ s, int r, int c, __half* out) {
    if ((unsigned)r < IH && (unsigned)c < IW) {
        const float* p = s + (r * IW + c) * 3;
        out[0] = __float2half(p[0]);
        out[1] = __float2half(p[1]);
        out[2] = __float2half(p[2]);
        out[3] = __float2half(0.f);
    } else {
        out[0] = out[1] = out[2] = out[3] = __float2half(0.f);
    }
}

__global__ void pack_src_kernel(const float* __restrict__ src) {
    int t0 = blockIdx.x * blockDim.x + threadIdx.x;
#pragma unroll
    for (int h = 0; h < 2; h++) {
        int t = t0 + h * (2 * COPYSZ);
        if (t >= 4 * COPYSZ) return;
        int c   = t / COPYSZ;
        int rem = t % COPYSZ;
        int ky = rem / QSTRIDE;
        int kx = rem % QSTRIDE;
        int py = c >> 1, px = c & 1;
        int r0 = 2 * ky - py;
        int c0 = 2 * kx - px;
        __align__(32) __half hh[16];
        px_fetch(src, r0,     c0,     hh + 0);
        px_fetch(src, r0,     c0 + 1, hh + 4);
        px_fetch(src, r0 + 1, c0,     hh + 8);
        px_fetch(src, r0 + 1, c0 + 1, hh + 12);
        g_quads[t] = *reinterpret_cast<Quad*>(hh);
    }
}

__device__ __forceinline__ __half2 u2h(unsigned v) {
    return *reinterpret_cast<__half2*>(&v);
}

__global__ void __launch_bounds__(DTHREADS) deform_kernel(
    const float* __restrict__ motions, float* __restrict__ out) {
    const float4* m4 = reinterpret_cast<const float4*>(motions);
    float4* o4base = reinterpret_cast<float4*>(out);

    for (int t = blockIdx.x * DTHREADS + threadIdx.x; t < NGROUPS;
         t += DBLOCKS * DTHREADS) {
        float4 m0 = __ldcs(&m4[(size_t)t * 2 + 0]);   // x0 y0 x1 y1
        float4 m1 = __ldcs(&m4[(size_t)t * 2 + 1]);   // x2 y2 x3 y3

        float gx[4] = {m0.x, m0.z, m1.x, m1.z};
        float gy[4] = {m0.y, m0.w, m1.y, m1.w};

        float fx[4], fy[4];
        const Quad* qp[4];
#pragma unroll
        for (int s = 0; s < 4; s++) {
            float x = fmaf(gx[s], 128.f, 127.5f);   // [-0.5, 255.5)
            float y = fmaf(gy[s], 128.f, 127.5f);
            int xw = __float2int_rd(x);   // [-1, 255]
            int yn = __float2int_rd(y);   // [-1, 255]
            fx[s] = x - (float)xw;
            fy[s] = y - (float)yn;
            int py = yn & 1, px = xw & 1;
            int ky = (yn + py) >> 1;
            int kx = (xw + px) >> 1;
            qp[s] = &g_quads[((py << 1) | px) * COPYSZ + ky * QSTRIDE + kx];
        }

        // 4 independent divergent 256-bit gathers, back-to-back.
        unsigned q[4][8];
#pragma unroll
        for (int s = 0; s < 4; s++) {
            asm("ld.global.nc.v8.b32 {%0,%1,%2,%3,%4,%5,%6,%7}, [%8];"
                : "=r"(q[s][0]), "=r"(q[s][1]), "=r"(q[s][2]), "=r"(q[s][3]),
                  "=r"(q[s][4]), "=r"(q[s][5]), "=r"(q[s][6]), "=r"(q[s][7])
                : "l"(qp[s]));
        }

        float r[12];
#pragma unroll
        for (int s = 0; s < 4; s++) {
            float wnw = (1.f - fy[s]) * (1.f - fx[s]);
            float wne = (1.f - fy[s]) * fx[s];
            float wsw = fy[s] * (1.f - fx[s]);
            float wse = fy[s] * fx[s];
            // replicated half2 weights
            __half2 hnw = __float2half2_rn(wnw);
            __half2 hne = __float2half2_rn(wne);
            __half2 hsw = __float2half2_rn(wsw);
            __half2 hse = __float2half2_rn(wse);

            // rg accumulate in half2: q[.][0]=NW(r,g) 2=NE 4=SW 6=SE
            __half2 acc_rg = __hmul2(hnw, u2h(q[s][0]));
            acc_rg = __hfma2(hne, u2h(q[s][2]), acc_rg);
            acc_rg = __hfma2(hsw, u2h(q[s][4]), acc_rg);
            acc_rg = __hfma2(hse, u2h(q[s][6]), acc_rg);
            // b (packed as (b,0)): words 1,3,5,7
            __half2 acc_b = __hmul2(hnw, u2h(q[s][1]));
            acc_b = __hfma2(hne, u2h(q[s][3]), acc_b);
            acc_b = __hfma2(hsw, u2h(q[s][5]), acc_b);
            acc_b = __hfma2(hse, u2h(q[s][7]), acc_b);

            float2 rg = __half22float2(acc_rg);
            r[s * 3 + 0] = rg.x;
            r[s * 3 + 1] = rg.y;
            r[s * 3 + 2] = __low2float(acc_b);
        }

        float4* o4 = o4base + (size_t)t * 3;
        __stcs(&o4[0], make_float4(r[0], r[1], r[2],  r[3]));
        __stcs(&o4[1], make_float4(r[4], r[5], r[6],  r[7]));
        __stcs(&o4[2], make_float4(r[8], r[9], r[10], r[11]));
    }
}

extern "C" void kernel_launch(void* const* d_in, const int* in_sizes, int n_in,
                              void* d_out, int out_size) {
    const float* source  = (const float*)d_in[0];
    const float* motions = (const float*)d_in[1];
    if (n_in >= 2 && in_sizes[0] != SRC_ELEMS) {
        source  = (const float*)d_in[1];
        motions = (const float*)d_in[0];
    }

    pack_src_kernel<<<(2 * COPYSZ + 255) / 256, 256>>>(source);
    deform_kernel<<<DBLOCKS, DTHREADS>>>(motions, (float*)d_out);
}